// round 10
// baseline (speedup 1.0000x reference)
#include <cuda_runtime.h>
#include <cuda_fp16.h>
#include <stdint.h>
#include <math.h>

#define BB 8
#define HH 64
#define WW 64
#define CC 256
#define NPIX (BB*HH*WW)          // 32768

// ---------------- device scratch ----------------
__device__ __half g_yh[NPIX*CC];   // blurred x, fp16
__device__ __half g_Wh[CC*CC];     // fused weight W = proj_w @ v_w, fp16

// ---------------- helpers ----------------
__device__ __forceinline__ uint32_t smem_u32(const void* p) {
    uint32_t a;
    asm("{ .reg .u64 t; cvta.to.shared.u64 t, %1; cvt.u32.u64 %0, t; }" : "=r"(a) : "l"(p));
    return a;
}
__device__ __forceinline__ uint64_t gmem_u64(const void* p) {
    uint64_t a;
    asm("cvta.to.global.u64 %0, %1;" : "=l"(a) : "l"(p));
    return a;
}
#define CP_ASYNC16(sa, ga) \
    asm volatile("cp.async.cg.shared.global [%0], [%1], 16;" :: "r"(sa), "l"(ga))
#define CP_COMMIT() asm volatile("cp.async.commit_group;")
#define CP_WAIT(n)  asm volatile("cp.async.wait_group %0;" :: "n"(n))

#define LDMATRIX_X4(r0, r1, r2, r3, addr) \
    asm volatile("ldmatrix.sync.aligned.m8n8.x4.shared.b16 {%0,%1,%2,%3}, [%4];" \
        : "=r"(r0), "=r"(r1), "=r"(r2), "=r"(r3) : "r"(addr))

#define MMA_16816_F16(c, a, b0, b1) \
    asm volatile("mma.sync.aligned.m16n8k16.row.col.f32.f16.f16.f32 " \
        "{%0,%1,%2,%3}, {%4,%5,%6,%7}, {%8,%9}, {%0,%1,%2,%3};" \
        : "+f"((c)[0]), "+f"((c)[1]), "+f"((c)[2]), "+f"((c)[3]) \
        : "r"((a)[0]), "r"((a)[1]), "r"((a)[2]), "r"((a)[3]), "r"(b0), "r"(b1))

// ============================================================================
// K1: prep.
//  Blocks [0,8192): blur -> g_yh (fp16). One thread per (pixel, c4).
//    9 independent loads in flight (MLP 9); x re-reads hit L2. No barriers.
//  Blocks [8192,8256): W = proj_w @ v_w -> g_Wh (fp16).
// ============================================================================
__global__ __launch_bounds__(256) void prep_kernel(const float* __restrict__ x,
                                                   const float* __restrict__ vw,
                                                   const float* __restrict__ pw) {
    int bid = blockIdx.x;
    int tid = threadIdx.x;
    if (bid < 8192) {
        int t  = bid * 256 + tid;
        int c4 = t & 63;
        int p  = t >> 6;
        int w  = p & 63;
        int hb = p >> 6;
        int h  = hb & 63;
        int b  = hb >> 6;
        const float e  = 2.718281828459045f;
        const float wo = 1.0f / (e + 8.0f);
        const float ws = e * wo;
        const float4* x4 = (const float4*)x;
        float4 acc = make_float4(0.f, 0.f, 0.f, 0.f);
        #pragma unroll
        for (int i = 0; i < 3; i++) {
            int hh = h + i - 1;
            if (hh < 0 || hh >= HH) continue;
            #pragma unroll
            for (int j = 0; j < 3; j++) {
                int ww = w + j - 1;
                if (ww < 0 || ww >= WW) continue;
                float wgt = (i == 0 && j == 0) ? ws : wo;
                float4 v = x4[((b * HH + hh) * WW + ww) * 64 + c4];
                acc.x += wgt * v.x; acc.y += wgt * v.y;
                acc.z += wgt * v.z; acc.w += wgt * v.w;
            }
        }
        union { __half h4[4]; uint2 u; } Hi;
        Hi.h4[0] = __float2half_rn(acc.x);
        Hi.h4[1] = __float2half_rn(acc.y);
        Hi.h4[2] = __float2half_rn(acc.z);
        Hi.h4[3] = __float2half_rn(acc.w);
        ((uint2*)g_yh)[t] = Hi.u;
    } else {
        int q  = bid - 8192;
        int e0 = (q >> 3) * 32;
        int c0 = (q & 7) * 32;
        int er = e0 + (tid >> 3);
        int cc = c0 + (tid & 7) * 4;
        float a0 = 0.f, a1 = 0.f, a2 = 0.f, a3 = 0.f;
        const float* prow = pw + er * 256;
        #pragma unroll 8
        for (int d = 0; d < 256; d++) {
            float a = prow[d];
            float4 v = *(const float4*)(vw + d * 256 + cc);
            a0 += a * v.x; a1 += a * v.y; a2 += a * v.z; a3 += a * v.w;
        }
        union { __half h4[4]; uint2 u; } Hi;
        Hi.h4[0] = __float2half_rn(a0);
        Hi.h4[1] = __float2half_rn(a1);
        Hi.h4[2] = __float2half_rn(a2);
        Hi.h4[3] = __float2half_rn(a3);
        *(uint2*)(g_Wh + er * 256 + cc) = Hi.u;
    }
}

// ============================================================================
// K2: out = y @ W^T + bias; single fp16 term, fp32 accum.  (UNCHANGED from R9)
//   CTA 128x128. B (weight N-tile, full K=256) resident in smem, loaded once.
//   A streamed in K=32 chunks through a 3-slot cp.async ring.
//   8 warps (4Mx2N), warp tile 32x64. One syncthreads per chunk.
// ============================================================================
#define B_STRIDE 528
#define B_BYTES  (128 * B_STRIDE)        // 67584
#define A_SLOT   10240                   // 128 * 80
#define SMEM_TOTAL (B_BYTES + 3 * A_SLOT)  // 98304 (96KB) -> 2 CTAs/SM

__global__ __launch_bounds__(256, 2) void gemm_mma_kernel(const float* __restrict__ bias,
                                                          float* __restrict__ out) {
    extern __shared__ __align__(16) char smem[];
    uint32_t sbB = smem_u32(smem);
    uint32_t sbA = sbB + B_BYTES;
    int tid  = threadIdx.x;
    int wid  = tid >> 5;
    int lane = tid & 31;
    int bn = blockIdx.x * 128;
    int bm = blockIdx.y * 128;
    int wn = wid & 1;              // 2 N slices of 64
    int wm = wid >> 1;             // 4 M slices of 32

    float acc[2][8][4] = {};

    // ---- one-time B load: 128 rows x 512B ----
    #pragma unroll
    for (int i = 0; i < 16; i++) {
        int q = i * 256 + tid;          // 4096 16B-chunks
        int row = q >> 5, c16 = q & 31;
        CP_ASYNC16(sbB + row * B_STRIDE + c16 * 16,
                   gmem_u64(g_Wh + (size_t)(bn + row) * 256 + c16 * 8));
    }

    auto issue_A = [&](int kc, int slot) {
        #pragma unroll
        for (int j = 0; j < 2; j++) {
            int q = tid * 2 + j;        // 512 chunks
            int row = q >> 2, seg = q & 3;
            CP_ASYNC16(sbA + slot * A_SLOT + row * 80 + seg * 16,
                       gmem_u64(g_yh + (size_t)(bm + row) * 256 + kc * 32 + seg * 8));
        }
    };

    issue_A(0, 0); CP_COMMIT();     // C0 = B + A0
    issue_A(1, 1); CP_COMMIT();     // C1 = A1

    #pragma unroll 1
    for (int kc = 0; kc < 8; kc++) {
        if (kc < 7) { CP_WAIT(1); } else { CP_WAIT(0); }
        __syncthreads();
        if (kc + 2 < 8) { issue_A(kc + 2, (kc + 2) % 3); CP_COMMIT(); }

        uint32_t aB = sbA + (kc % 3) * A_SLOT;

        #pragma unroll
        for (int ks = 0; ks < 2; ks++) {
            uint32_t af[2][4], bf[4][4];
            #pragma unroll
            for (int mi = 0; mi < 2; mi++) {
                int row = wm * 32 + mi * 16 + (lane & 15);
                uint32_t ao = row * 80 + ks * 32 + (lane >> 4) * 16;
                LDMATRIX_X4(af[mi][0], af[mi][1], af[mi][2], af[mi][3], aB + ao);
            }
            #pragma unroll
            for (int ng = 0; ng < 4; ng++) {
                int row = wn * 64 + ng * 16 + (lane & 15);
                uint32_t bo = row * B_STRIDE + kc * 64 + ks * 32 + (lane >> 4) * 16;
                LDMATRIX_X4(bf[ng][0], bf[ng][1], bf[ng][2], bf[ng][3], sbB + bo);
            }
            #pragma unroll
            for (int mi = 0; mi < 2; mi++)
                #pragma unroll
                for (int ng = 0; ng < 4; ng++) {
                    MMA_16816_F16(acc[mi][ng * 2 + 0], af[mi], bf[ng][0], bf[ng][2]);
                    MMA_16816_F16(acc[mi][ng * 2 + 1], af[mi], bf[ng][1], bf[ng][3]);
                }
        }
    }

    // ---- epilogue ----
    #pragma unroll
    for (int mi = 0; mi < 2; mi++) {
        int r0 = bm + wm * 32 + mi * 16 + (lane >> 2);
        #pragma unroll
        for (int ni = 0; ni < 8; ni++) {
            int c = bn + wn * 64 + ni * 8 + (lane & 3) * 2;
            float b0 = __ldg(bias + c);
            float b1 = __ldg(bias + c + 1);
            float2 o0 = make_float2(acc[mi][ni][0] + b0, acc[mi][ni][1] + b1);
            float2 o1 = make_float2(acc[mi][ni][2] + b0, acc[mi][ni][3] + b1);
            *(float2*)(out + (size_t)r0 * 256 + c) = o0;
            *(float2*)(out + (size_t)(r0 + 8) * 256 + c) = o1;
        }
    }
}

// ============================================================================
extern "C" void kernel_launch(void* const* d_in, const int* in_sizes, int n_in,
                              void* d_out, int out_size) {
    const float* x  = (const float*)d_in[0];
    const float* vw = (const float*)d_in[1];
    const float* pw = (const float*)d_in[2];
    const float* pb = (const float*)d_in[3];
    float* out = (float*)d_out;

    cudaFuncSetAttribute(gemm_mma_kernel, cudaFuncAttributeMaxDynamicSharedMemorySize, SMEM_TOTAL);

    prep_kernel<<<8192 + 64, 256>>>(x, vw, pw);
    gemm_mma_kernel<<<dim3(2, 256), 256, SMEM_TOTAL>>>(pb, out);
}

// round 11
// speedup vs baseline: 1.4096x; 1.4096x over previous
#include <cuda_runtime.h>
#include <cuda_fp16.h>
#include <stdint.h>
#include <math.h>

#define BB 8
#define HH 64
#define WW 64
#define CC 256
#define NPIX (BB*HH*WW)          // 32768

// ---------------- device scratch ----------------
__device__ __half g_yh[NPIX*CC];   // blurred x, fp16
__device__ __half g_Wh[CC*CC];     // fused weight W = proj_w @ v_w, fp16

// ---------------- helpers ----------------
__device__ __forceinline__ uint32_t smem_u32(const void* p) {
    uint32_t a;
    asm("{ .reg .u64 t; cvta.to.shared.u64 t, %1; cvt.u32.u64 %0, t; }" : "=r"(a) : "l"(p));
    return a;
}
__device__ __forceinline__ uint64_t gmem_u64(const void* p) {
    uint64_t a;
    asm("cvta.to.global.u64 %0, %1;" : "=l"(a) : "l"(p));
    return a;
}
#define CP_ASYNC16(sa, ga) \
    asm volatile("cp.async.cg.shared.global [%0], [%1], 16;" :: "r"(sa), "l"(ga))
#define CP_COMMIT() asm volatile("cp.async.commit_group;")
#define CP_WAIT(n)  asm volatile("cp.async.wait_group %0;" :: "n"(n))

#define LDMATRIX_X4(r0, r1, r2, r3, addr) \
    asm volatile("ldmatrix.sync.aligned.m8n8.x4.shared.b16 {%0,%1,%2,%3}, [%4];" \
        : "=r"(r0), "=r"(r1), "=r"(r2), "=r"(r3) : "r"(addr))

#define MMA_16816_F16(c, a, b0, b1) \
    asm volatile("mma.sync.aligned.m16n8k16.row.col.f32.f16.f16.f32 " \
        "{%0,%1,%2,%3}, {%4,%5,%6,%7}, {%8,%9}, {%0,%1,%2,%3};" \
        : "+f"((c)[0]), "+f"((c)[1]), "+f"((c)[2]), "+f"((c)[3]) \
        : "r"((a)[0]), "r"((a)[1]), "r"((a)[2]), "r"((a)[3]), "r"(b0), "r"(b1))

static __device__ __forceinline__ float4 f4add(float4 a, float4 b) {
    return make_float4(a.x+b.x, a.y+b.y, a.z+b.z, a.w+b.w);
}

// ============================================================================
// K1: prep.
//  Blocks [0,512): blur -> g_yh. Block = (b, 16-row seg, 4-c4 cgroup).
//   6-slot smem row ring, register load-queue with PREFETCH DISTANCE 5:
//   the row STS'd at iteration i was loaded 5 barriers ago -> DRAM latency
//   fully hidden; barriers no longer expose loads.
//  Blocks [512,576): W = proj_w @ v_w -> g_Wh (fp16).
// ============================================================================
__global__ __launch_bounds__(256) void prep_kernel(const float* __restrict__ x,
                                                   const float* __restrict__ vw,
                                                   const float* __restrict__ pw) {
    __shared__ float4 srow[6 * 256];    // 6 slots x (64 w x 4 c4) = 24KB
    int bid = blockIdx.x;
    int tid = threadIdx.x;
    if (bid < 512) {
        int b   = bid >> 6;           // 8
        int seg = (bid >> 4) & 3;     // 4 segments of 16 rows
        int cg  = bid & 15;           // 16 channel groups of 4 c4
        int h0  = seg * 16;
        int w   = tid >> 2;           // 0..63
        int c4i = tid & 3;
        int c4  = cg * 4 + c4i;
        const float e  = 2.718281828459045f;
        const float wo = 1.0f / (e + 8.0f);
        const float wd = e * wo - wo;
        const float4 Z = make_float4(0.f, 0.f, 0.f, 0.f);
        const float4* x4 = (const float4*)x;

        auto gload = [&](int r) -> float4 {
            if (r < 0 || r >= HH) return Z;
            return x4[(((size_t)b * HH + r) * WW + w) * 64 + c4];
        };

        float4 q[6];
        // prologue: rows h0-1 .. h0+3 in the queue (5 loads in flight)
        #pragma unroll
        for (int j = 0; j < 5; j++) q[j] = gload(h0 - 1 + j);

        float4 hs0 = Z, hs1 = Z, xl0 = Z, xl1 = Z;

        #pragma unroll
        for (int i = 0; i < 18; i++) {          // row r = h0-1+i
            int slot = i % 6;
            srow[slot * 256 + w * 4 + c4i] = q[i % 6];
            if (i + 5 < 18) q[(i + 5) % 6] = gload(h0 - 1 + i + 5);  // dist-5 prefetch
            __syncthreads();

            float4 xl = (w > 0)  ? srow[slot * 256 + (w - 1) * 4 + c4i] : Z;
            float4 xc =            srow[slot * 256 + w * 4 + c4i];
            float4 xr = (w < 63) ? srow[slot * 256 + (w + 1) * 4 + c4i] : Z;
            float4 hsum = f4add(f4add(xl, xc), xr);

            if (i >= 2) {
                int h = h0 + i - 2;
                float4 o;
                o.x = wo * (hs0.x + hs1.x + hsum.x) + wd * xl0.x;
                o.y = wo * (hs0.y + hs1.y + hsum.y) + wd * xl0.y;
                o.z = wo * (hs0.z + hs1.z + hsum.z) + wd * xl0.z;
                o.w = wo * (hs0.w + hs1.w + hsum.w) + wd * xl0.w;
                union { __half h4[4]; uint2 u; } Hi;
                Hi.h4[0] = __float2half_rn(o.x);
                Hi.h4[1] = __float2half_rn(o.y);
                Hi.h4[2] = __float2half_rn(o.z);
                Hi.h4[3] = __float2half_rn(o.w);
                size_t oq = (((size_t)b * HH + h) * WW + w) * 64 + c4;  // uint2 units
                ((uint2*)g_yh)[oq] = Hi.u;
            }
            hs0 = hs1; hs1 = hsum;
            xl0 = xl1; xl1 = xl;
        }
    } else {
        int q  = bid - 512;
        int e0 = (q >> 3) * 32;
        int c0 = (q & 7) * 32;
        int er = e0 + (tid >> 3);
        int cc = c0 + (tid & 7) * 4;
        float a0 = 0.f, a1 = 0.f, a2 = 0.f, a3 = 0.f;
        const float* prow = pw + er * 256;
        #pragma unroll 8
        for (int d = 0; d < 256; d++) {
            float a = prow[d];
            float4 v = *(const float4*)(vw + d * 256 + cc);
            a0 += a * v.x; a1 += a * v.y; a2 += a * v.z; a3 += a * v.w;
        }
        union { __half h4[4]; uint2 u; } Hi;
        Hi.h4[0] = __float2half_rn(a0);
        Hi.h4[1] = __float2half_rn(a1);
        Hi.h4[2] = __float2half_rn(a2);
        Hi.h4[3] = __float2half_rn(a3);
        *(uint2*)(g_Wh + er * 256 + cc) = Hi.u;
    }
}

// ============================================================================
// K2: out = y @ W^T + bias; single fp16 term, fp32 accum.  (UNCHANGED, 29.6us)
//   CTA 128x128. B (weight N-tile, full K=256) resident in smem, loaded once.
//   A streamed in K=32 chunks through a 3-slot cp.async ring.
//   8 warps (4Mx2N), warp tile 32x64. One syncthreads per chunk.
// ============================================================================
#define B_STRIDE 528
#define B_BYTES  (128 * B_STRIDE)        // 67584
#define A_SLOT   10240                   // 128 * 80
#define SMEM_TOTAL (B_BYTES + 3 * A_SLOT)  // 98304 (96KB) -> 2 CTAs/SM

__global__ __launch_bounds__(256, 2) void gemm_mma_kernel(const float* __restrict__ bias,
                                                          float* __restrict__ out) {
    extern __shared__ __align__(16) char smem[];
    uint32_t sbB = smem_u32(smem);
    uint32_t sbA = sbB + B_BYTES;
    int tid  = threadIdx.x;
    int wid  = tid >> 5;
    int lane = tid & 31;
    int bn = blockIdx.x * 128;
    int bm = blockIdx.y * 128;
    int wn = wid & 1;              // 2 N slices of 64
    int wm = wid >> 1;             // 4 M slices of 32

    float acc[2][8][4] = {};

    // ---- one-time B load: 128 rows x 512B ----
    #pragma unroll
    for (int i = 0; i < 16; i++) {
        int q = i * 256 + tid;          // 4096 16B-chunks
        int row = q >> 5, c16 = q & 31;
        CP_ASYNC16(sbB + row * B_STRIDE + c16 * 16,
                   gmem_u64(g_Wh + (size_t)(bn + row) * 256 + c16 * 8));
    }

    auto issue_A = [&](int kc, int slot) {
        #pragma unroll
        for (int j = 0; j < 2; j++) {
            int q = tid * 2 + j;        // 512 chunks
            int row = q >> 2, seg = q & 3;
            CP_ASYNC16(sbA + slot * A_SLOT + row * 80 + seg * 16,
                       gmem_u64(g_yh + (size_t)(bm + row) * 256 + kc * 32 + seg * 8));
        }
    };

    issue_A(0, 0); CP_COMMIT();     // C0 = B + A0
    issue_A(1, 1); CP_COMMIT();     // C1 = A1

    #pragma unroll 1
    for (int kc = 0; kc < 8; kc++) {
        if (kc < 7) { CP_WAIT(1); } else { CP_WAIT(0); }
        __syncthreads();
        if (kc + 2 < 8) { issue_A(kc + 2, (kc + 2) % 3); CP_COMMIT(); }

        uint32_t aB = sbA + (kc % 3) * A_SLOT;

        #pragma unroll
        for (int ks = 0; ks < 2; ks++) {
            uint32_t af[2][4], bf[4][4];
            #pragma unroll
            for (int mi = 0; mi < 2; mi++) {
                int row = wm * 32 + mi * 16 + (lane & 15);
                uint32_t ao = row * 80 + ks * 32 + (lane >> 4) * 16;
                LDMATRIX_X4(af[mi][0], af[mi][1], af[mi][2], af[mi][3], aB + ao);
            }
            #pragma unroll
            for (int ng = 0; ng < 4; ng++) {
                int row = wn * 64 + ng * 16 + (lane & 15);
                uint32_t bo = row * B_STRIDE + kc * 64 + ks * 32 + (lane >> 4) * 16;
                LDMATRIX_X4(bf[ng][0], bf[ng][1], bf[ng][2], bf[ng][3], sbB + bo);
            }
            #pragma unroll
            for (int mi = 0; mi < 2; mi++)
                #pragma unroll
                for (int ng = 0; ng < 4; ng++) {
                    MMA_16816_F16(acc[mi][ng * 2 + 0], af[mi], bf[ng][0], bf[ng][2]);
                    MMA_16816_F16(acc[mi][ng * 2 + 1], af[mi], bf[ng][1], bf[ng][3]);
                }
        }
    }

    // ---- epilogue ----
    #pragma unroll
    for (int mi = 0; mi < 2; mi++) {
        int r0 = bm + wm * 32 + mi * 16 + (lane >> 2);
        #pragma unroll
        for (int ni = 0; ni < 8; ni++) {
            int c = bn + wn * 64 + ni * 8 + (lane & 3) * 2;
            float b0 = __ldg(bias + c);
            float b1 = __ldg(bias + c + 1);
            float2 o0 = make_float2(acc[mi][ni][0] + b0, acc[mi][ni][1] + b1);
            float2 o1 = make_float2(acc[mi][ni][2] + b0, acc[mi][ni][3] + b1);
            *(float2*)(out + (size_t)r0 * 256 + c) = o0;
            *(float2*)(out + (size_t)(r0 + 8) * 256 + c) = o1;
        }
    }
}

// ============================================================================
extern "C" void kernel_launch(void* const* d_in, const int* in_sizes, int n_in,
                              void* d_out, int out_size) {
    const float* x  = (const float*)d_in[0];
    const float* vw = (const float*)d_in[1];
    const float* pw = (const float*)d_in[2];
    const float* pb = (const float*)d_in[3];
    float* out = (float*)d_out;

    cudaFuncSetAttribute(gemm_mma_kernel, cudaFuncAttributeMaxDynamicSharedMemorySize, SMEM_TOTAL);

    prep_kernel<<<512 + 64, 256>>>(x, vw, pw);
    gemm_mma_kernel<<<dim3(2, 256), 256, SMEM_TOTAL>>>(pb, out);
}

// round 13
// speedup vs baseline: 1.6682x; 1.1835x over previous
#include <cuda_runtime.h>
#include <cuda_fp16.h>
#include <stdint.h>
#include <math.h>

#define BB 8
#define HH 64
#define WW 64
#define CC 256
#define NPIX (BB*HH*WW)          // 32768

// ---------------- device scratch ----------------
__device__ __half g_yh[NPIX*CC];   // blurred x, fp16
__device__ __half g_Wh[CC*CC];     // fused weight W = proj_w @ v_w, fp16

// ---------------- helpers ----------------
__device__ __forceinline__ uint32_t smem_u32(const void* p) {
    uint32_t a;
    asm("{ .reg .u64 t; cvta.to.shared.u64 t, %1; cvt.u32.u64 %0, t; }" : "=r"(a) : "l"(p));
    return a;
}
__device__ __forceinline__ uint64_t gmem_u64(const void* p) {
    uint64_t a;
    asm("cvta.to.global.u64 %0, %1;" : "=l"(a) : "l"(p));
    return a;
}
#define CP_ASYNC16(sa, ga) \
    asm volatile("cp.async.cg.shared.global [%0], [%1], 16;" :: "r"(sa), "l"(ga))
#define CP_COMMIT() asm volatile("cp.async.commit_group;")
#define CP_WAIT(n)  asm volatile("cp.async.wait_group %0;" :: "n"(n))

#define LDMATRIX_X4(r0, r1, r2, r3, addr) \
    asm volatile("ldmatrix.sync.aligned.m8n8.x4.shared.b16 {%0,%1,%2,%3}, [%4];" \
        : "=r"(r0), "=r"(r1), "=r"(r2), "=r"(r3) : "r"(addr))

#define MMA_16816_F16(c, a, b0, b1) \
    asm volatile("mma.sync.aligned.m16n8k16.row.col.f32.f16.f16.f32 " \
        "{%0,%1,%2,%3}, {%4,%5,%6,%7}, {%8,%9}, {%0,%1,%2,%3};" \
        : "+f"((c)[0]), "+f"((c)[1]), "+f"((c)[2]), "+f"((c)[3]) \
        : "r"((a)[0]), "r"((a)[1]), "r"((a)[2]), "r"((a)[3]), "r"(b0), "r"(b1))

static __device__ __forceinline__ float4 f4add(float4 a, float4 b) {
    return make_float4(a.x+b.x, a.y+b.y, a.z+b.z, a.w+b.w);
}

// ============================================================================
// K1: prep.
//  Blocks [0,512): blur -> g_yh. Block = (b, 16-row seg, 4-c4 cgroup).
//   6-slot smem row ring (unchanged from R11; not the critical path).
//  Blocks [512,576): W = proj_w @ v_w -> g_Wh. NEW: smem-staged vw panel
//   (chunk-major, stride-257-float4 padding -> conflict-free), parallel
//   panel load with MLP 8, then LDS+FFMA compute. Was the 28us critical path.
// ============================================================================
__global__ __launch_bounds__(256) void prep_kernel(const float* __restrict__ x,
                                                   const float* __restrict__ vw,
                                                   const float* __restrict__ pw) {
    __shared__ __align__(16) char sbuf[8 * 257 * 16];   // 32896B; blur uses 24576B
    int bid = blockIdx.x;
    int tid = threadIdx.x;
    if (bid < 512) {
        float4* srow = (float4*)sbuf;     // 6 slots x 256 float4
        int b   = bid >> 6;
        int seg = (bid >> 4) & 3;
        int cg  = bid & 15;
        int h0  = seg * 16;
        int w   = tid >> 2;
        int c4i = tid & 3;
        int c4  = cg * 4 + c4i;
        const float e  = 2.718281828459045f;
        const float wo = 1.0f / (e + 8.0f);
        const float wd = e * wo - wo;
        const float4 Z = make_float4(0.f, 0.f, 0.f, 0.f);
        const float4* x4 = (const float4*)x;

        auto gload = [&](int r) -> float4 {
            if (r < 0 || r >= HH) return Z;
            return x4[(((size_t)b * HH + r) * WW + w) * 64 + c4];
        };

        float4 q[6];
        #pragma unroll
        for (int j = 0; j < 5; j++) q[j] = gload(h0 - 1 + j);

        float4 hs0 = Z, hs1 = Z, xl0 = Z, xl1 = Z;

        #pragma unroll
        for (int i = 0; i < 18; i++) {          // row r = h0-1+i
            int slot = i % 6;
            srow[slot * 256 + w * 4 + c4i] = q[i % 6];
            if (i + 5 < 18) q[(i + 5) % 6] = gload(h0 - 1 + i + 5);
            __syncthreads();

            float4 xl = (w > 0)  ? srow[slot * 256 + (w - 1) * 4 + c4i] : Z;
            float4 xc =            srow[slot * 256 + w * 4 + c4i];
            float4 xr = (w < 63) ? srow[slot * 256 + (w + 1) * 4 + c4i] : Z;
            float4 hsum = f4add(f4add(xl, xc), xr);

            if (i >= 2) {
                int h = h0 + i - 2;
                float4 o;
                o.x = wo * (hs0.x + hs1.x + hsum.x) + wd * xl0.x;
                o.y = wo * (hs0.y + hs1.y + hsum.y) + wd * xl0.y;
                o.z = wo * (hs0.z + hs1.z + hsum.z) + wd * xl0.z;
                o.w = wo * (hs0.w + hs1.w + hsum.w) + wd * xl0.w;
                union { __half h4[4]; uint2 u; } Hi;
                Hi.h4[0] = __float2half_rn(o.x);
                Hi.h4[1] = __float2half_rn(o.y);
                Hi.h4[2] = __float2half_rn(o.z);
                Hi.h4[3] = __float2half_rn(o.w);
                size_t oq = (((size_t)b * HH + h) * WW + w) * 64 + c4;
                ((uint2*)g_yh)[oq] = Hi.u;
            }
            hs0 = hs1; hs1 = hsum;
            xl0 = xl1; xl1 = xl;
        }
    } else {
        // ---- W-fuse v2: smem-staged vw panel ----
        float4* Bs4 = (float4*)sbuf;          // [chunk 0..7][d 0..255], stride 257
        int q  = bid - 512;
        int e0 = (q >> 3) * 32;
        int c0 = (q & 7) * 32;
        const float4* vw4 = (const float4*)vw;
        // stage vw[d=tid][c0 .. c0+31]: 8 independent float4 loads per thread
        #pragma unroll
        for (int j = 0; j < 8; j++)
            Bs4[j * 257 + tid] = vw4[tid * 64 + (c0 >> 2) + j];
        __syncthreads();

        int er = e0 + (tid >> 3);
        int c8 = tid & 7;
        const float* prow = pw + er * 256;
        const float4* Bcol = Bs4 + c8 * 257;
        float a0 = 0.f, a1 = 0.f, a2 = 0.f, a3 = 0.f;
        #pragma unroll 8
        for (int d = 0; d < 256; d++) {
            float a = prow[d];
            float4 bv = Bcol[d];
            a0 += a * bv.x; a1 += a * bv.y; a2 += a * bv.z; a3 += a * bv.w;
        }
        union { __half h4[4]; uint2 u; } Hi;
        Hi.h4[0] = __float2half_rn(a0);
        Hi.h4[1] = __float2half_rn(a1);
        Hi.h4[2] = __float2half_rn(a2);
        Hi.h4[3] = __float2half_rn(a3);
        *(uint2*)(g_Wh + er * 256 + c0 + c8 * 4) = Hi.u;
    }
}

// ============================================================================
// K2: out = y @ W^T + bias; single fp16 term, fp32 accum.  (UNCHANGED, 29.6us)
//   CTA 128x128. B (weight N-tile, full K=256) resident in smem, loaded once.
//   A streamed in K=32 chunks through a 3-slot cp.async ring.
// ============================================================================
#define B_STRIDE 528
#define B_BYTES  (128 * B_STRIDE)        // 67584
#define A_SLOT   10240                   // 128 * 80
#define SMEM_TOTAL (B_BYTES + 3 * A_SLOT)  // 98304 (96KB) -> 2 CTAs/SM

__global__ __launch_bounds__(256, 2) void gemm_mma_kernel(const float* __restrict__ bias,
                                                          float* __restrict__ out) {
    extern __shared__ __align__(16) char smem[];
    uint32_t sbB = smem_u32(smem);
    uint32_t sbA = sbB + B_BYTES;
    int tid  = threadIdx.x;
    int wid  = tid >> 5;
    int lane = tid & 31;
    int bn = blockIdx.x * 128;
    int bm = blockIdx.y * 128;
    int wn = wid & 1;
    int wm = wid >> 1;

    float acc[2][8][4] = {};

    #pragma unroll
    for (int i = 0; i < 16; i++) {
        int q = i * 256 + tid;
        int row = q >> 5, c16 = q & 31;
        CP_ASYNC16(sbB + row * B_STRIDE + c16 * 16,
                   gmem_u64(g_Wh + (size_t)(bn + row) * 256 + c16 * 8));
    }

    auto issue_A = [&](int kc, int slot) {
        #pragma unroll
        for (int j = 0; j < 2; j++) {
            int q = tid * 2 + j;
            int row = q >> 2, seg = q & 3;
            CP_ASYNC16(sbA + slot * A_SLOT + row * 80 + seg * 16,
                       gmem_u64(g_yh + (size_t)(bm + row) * 256 + kc * 32 + seg * 8));
        }
    };

    issue_A(0, 0); CP_COMMIT();
    issue_A(1, 1); CP_COMMIT();

    #pragma unroll 1
    for (int kc = 0; kc < 8; kc++) {
        if (kc < 7) { CP_WAIT(1); } else { CP_WAIT(0); }
        __syncthreads();
        if (kc + 2 < 8) { issue_A(kc + 2, (kc + 2) % 3); CP_COMMIT(); }

        uint32_t aB = sbA + (kc % 3) * A_SLOT;

        #pragma unroll
        for (int ks = 0; ks < 2; ks++) {
            uint32_t af[2][4], bf[4][4];
            #pragma unroll
            for (int mi = 0; mi < 2; mi++) {
                int row = wm * 32 + mi * 16 + (lane & 15);
                uint32_t ao = row * 80 + ks * 32 + (lane >> 4) * 16;
                LDMATRIX_X4(af[mi][0], af[mi][1], af[mi][2], af[mi][3], aB + ao);
            }
            #pragma unroll
            for (int ng = 0; ng < 4; ng++) {
                int row = wn * 64 + ng * 16 + (lane & 15);
                uint32_t bo = row * B_STRIDE + kc * 64 + ks * 32 + (lane >> 4) * 16;
                LDMATRIX_X4(bf[ng][0], bf[ng][1], bf[ng][2], bf[ng][3], sbB + bo);
            }
            #pragma unroll
            for (int mi = 0; mi < 2; mi++)
                #pragma unroll
                for (int ng = 0; ng < 4; ng++) {
                    MMA_16816_F16(acc[mi][ng * 2 + 0], af[mi], bf[ng][0], bf[ng][2]);
                    MMA_16816_F16(acc[mi][ng * 2 + 1], af[mi], bf[ng][1], bf[ng][3]);
                }
        }
    }

    #pragma unroll
    for (int mi = 0; mi < 2; mi++) {
        int r0 = bm + wm * 32 + mi * 16 + (lane >> 2);
        #pragma unroll
        for (int ni = 0; ni < 8; ni++) {
            int c = bn + wn * 64 + ni * 8 + (lane & 3) * 2;
            float b0 = __ldg(bias + c);
            float b1 = __ldg(bias + c + 1);
            float2 o0 = make_float2(acc[mi][ni][0] + b0, acc[mi][ni][1] + b1);
            float2 o1 = make_float2(acc[mi][ni][2] + b0, acc[mi][ni][3] + b1);
            *(float2*)(out + (size_t)r0 * 256 + c) = o0;
            *(float2*)(out + (size_t)(r0 + 8) * 256 + c) = o1;
        }
    }
}

// ============================================================================
extern "C" void kernel_launch(void* const* d_in, const int* in_sizes, int n_in,
                              void* d_out, int out_size) {
    const float* x  = (const float*)d_in[0];
    const float* vw = (const float*)d_in[1];
    const float* pw = (const float*)d_in[2];
    const float* pb = (const float*)d_in[3];
    float* out = (float*)d_out;

    cudaFuncSetAttribute(gemm_mma_kernel, cudaFuncAttributeMaxDynamicSharedMemorySize, SMEM_TOTAL);

    prep_kernel<<<512 + 64, 256>>>(x, vw, pw);
    gemm_mma_kernel<<<dim3(2, 256), 256, SMEM_TOTAL>>>(pb, out);
}

// round 14
// speedup vs baseline: 1.7418x; 1.0442x over previous
#include <cuda_runtime.h>
#include <cuda_fp16.h>
#include <stdint.h>
#include <math.h>

#define BB 8
#define HH 64
#define WW 64
#define CC 256
#define NPIX (BB*HH*WW)          // 32768

// ---------------- device scratch ----------------
__device__ __half g_yh[NPIX*CC];   // blurred x, fp16
__device__ __half g_Wh[CC*CC];     // fused weight W = proj_w @ v_w, fp16

// ---------------- helpers ----------------
__device__ __forceinline__ uint32_t smem_u32(const void* p) {
    uint32_t a;
    asm("{ .reg .u64 t; cvta.to.shared.u64 t, %1; cvt.u32.u64 %0, t; }" : "=r"(a) : "l"(p));
    return a;
}
__device__ __forceinline__ uint64_t gmem_u64(const void* p) {
    uint64_t a;
    asm("cvta.to.global.u64 %0, %1;" : "=l"(a) : "l"(p));
    return a;
}
#define CP_ASYNC16(sa, ga) \
    asm volatile("cp.async.cg.shared.global [%0], [%1], 16;" :: "r"(sa), "l"(ga))
#define CP_COMMIT() asm volatile("cp.async.commit_group;")
#define CP_WAIT(n)  asm volatile("cp.async.wait_group %0;" :: "n"(n))

#define LDMATRIX_X4(r0, r1, r2, r3, addr) \
    asm volatile("ldmatrix.sync.aligned.m8n8.x4.shared.b16 {%0,%1,%2,%3}, [%4];" \
        : "=r"(r0), "=r"(r1), "=r"(r2), "=r"(r3) : "r"(addr))

#define MMA_16816_F16(c, a, b0, b1) \
    asm volatile("mma.sync.aligned.m16n8k16.row.col.f32.f16.f16.f32 " \
        "{%0,%1,%2,%3}, {%4,%5,%6,%7}, {%8,%9}, {%0,%1,%2,%3};" \
        : "+f"((c)[0]), "+f"((c)[1]), "+f"((c)[2]), "+f"((c)[3]) \
        : "r"((a)[0]), "r"((a)[1]), "r"((a)[2]), "r"((a)[3]), "r"(b0), "r"(b1))

static __device__ __forceinline__ float4 f4add(float4 a, float4 b) {
    return make_float4(a.x+b.x, a.y+b.y, a.z+b.z, a.w+b.w);
}

// ============================================================================
// K1: prep.
//  Blocks [0,512): blur v3 -> g_yh. Block = (b, 8-row seg, 8-c4 cgroup).
//   Thread = (w, c4-pair) -> 32B contiguous loads; 4 threads = 128B/line.
//   Rows staged via cp.async into 5-slot smem ring (dist 3, wait_group(3)),
//   XOR swizzle (c4 ^ w) for conflict-free LDS. 10 rounds/block.
//  Blocks [512,576): W = proj_w @ v_w (smem-staged panel, from R13).
// ============================================================================
__global__ __launch_bounds__(256) void prep_kernel(const float* __restrict__ x,
                                                   const float* __restrict__ vw,
                                                   const float* __restrict__ pw) {
    __shared__ __align__(16) char sbuf[5 * 512 * 16];   // 40960B (blur); Wfuse uses 32896B
    int bid = blockIdx.x;
    int tid = threadIdx.x;
    if (bid < 512) {
        float4* srow = (float4*)sbuf;     // [slot][w*8 + s]
        uint32_t srow_u = smem_u32(sbuf);
        int b   = bid >> 6;               // 8
        int seg = (bid >> 3) & 7;         // 8 segments of 8 rows
        int cg  = bid & 7;                // 8 groups of 8 c4 (32 channels)
        int h0  = seg * 8;
        int w   = tid >> 2;               // 0..63
        int cp  = tid & 3;                // c4 pair
        int c4a = cg * 8 + cp * 2;        // global c4: c4a, c4a+1
        int s0  = (cp * 2) ^ (w & 7);     // swizzled local c4 of item 0
        int s1  = s0 ^ 1;
        const float e  = 2.718281828459045f;
        const float wo = 1.0f / (e + 8.0f);
        const float wd = e * wo - wo;
        const float4 Z = make_float4(0.f, 0.f, 0.f, 0.f);

        // stage row r into slot: cp.async (valid) or STS zeros; ALWAYS commit
        auto stage = [&](int r, int slot) {
            if (r >= 0 && r < HH) {
                uint64_t g0 = gmem_u64(x + (((size_t)b * HH + r) * WW + w) * 256 + c4a * 4);
                CP_ASYNC16(srow_u + (slot * 512 + w * 8 + s0) * 16, g0);
                CP_ASYNC16(srow_u + (slot * 512 + w * 8 + s1) * 16, g0 + 16);
            } else {
                srow[slot * 512 + w * 8 + s0] = Z;
                srow[slot * 512 + w * 8 + s1] = Z;
            }
            CP_COMMIT();
        };

        // prologue: rows h0-1, h0, h0+1 -> slots 0,1,2 (groups 0,1,2)
        stage(h0 - 1, 0);
        stage(h0,     1);
        stage(h0 + 1, 2);

        float4 hs0[2] = {Z, Z}, hs1[2] = {Z, Z};
        float4 xl0[2] = {Z, Z}, xl1[2] = {Z, Z};

        #pragma unroll
        for (int i = 0; i < 10; i++) {            // r = h0-1+i
            // stage row r+3 into slot (i+3)%5 (group 3+i); safe: that slot
            // was last read at round i-2, behind round i-1's barrier.
            stage((i <= 6) ? (h0 + 2 + i) : -1, (i + 3) % 5);
            CP_WAIT(3);                            // group i complete
            __syncthreads();

            int slot = i % 5;
            const float4* S = srow + slot * 512;
            #pragma unroll
            for (int t = 0; t < 2; t++) {
                int c4l = cp * 2 + t;
                float4 xl = (w > 0)  ? S[(w - 1) * 8 + (c4l ^ ((w - 1) & 7))] : Z;
                float4 xc =            S[w * 8 + (c4l ^ (w & 7))];
                float4 xr = (w < 63) ? S[(w + 1) * 8 + (c4l ^ ((w + 1) & 7))] : Z;
                float4 hsum = f4add(f4add(xl, xc), xr);

                if (i >= 2) {
                    float4 o;
                    o.x = wo * (hs0[t].x + hs1[t].x + hsum.x) + wd * xl0[t].x;
                    o.y = wo * (hs0[t].y + hs1[t].y + hsum.y) + wd * xl0[t].y;
                    o.z = wo * (hs0[t].z + hs1[t].z + hsum.z) + wd * xl0[t].z;
                    o.w = wo * (hs0[t].w + hs1[t].w + hsum.w) + wd * xl0[t].w;
                    union { __half h4[4]; uint2 u; } Hi;
                    Hi.h4[0] = __float2half_rn(o.x);
                    Hi.h4[1] = __float2half_rn(o.y);
                    Hi.h4[2] = __float2half_rn(o.z);
                    Hi.h4[3] = __float2half_rn(o.w);
                    int h = h0 + i - 2;
                    size_t oq = (((size_t)b * HH + h) * WW + w) * 64 + c4a + t;
                    ((uint2*)g_yh)[oq] = Hi.u;
                }
                hs0[t] = hs1[t]; hs1[t] = hsum;
                xl0[t] = xl1[t]; xl1[t] = xl;
            }
        }
    } else {
        // ---- W-fuse (R13, validated ~3us): smem-staged vw panel ----
        float4* Bs4 = (float4*)sbuf;          // [chunk 0..7][d 0..255], stride 257
        int q  = bid - 512;
        int e0 = (q >> 3) * 32;
        int c0 = (q & 7) * 32;
        const float4* vw4 = (const float4*)vw;
        #pragma unroll
        for (int j = 0; j < 8; j++)
            Bs4[j * 257 + tid] = vw4[tid * 64 + (c0 >> 2) + j];
        __syncthreads();

        int er = e0 + (tid >> 3);
        int c8 = tid & 7;
        const float* prow = pw + er * 256;
        const float4* Bcol = Bs4 + c8 * 257;
        float a0 = 0.f, a1 = 0.f, a2 = 0.f, a3 = 0.f;
        #pragma unroll 8
        for (int d = 0; d < 256; d++) {
            float a = prow[d];
            float4 bv = Bcol[d];
            a0 += a * bv.x; a1 += a * bv.y; a2 += a * bv.z; a3 += a * bv.w;
        }
        union { __half h4[4]; uint2 u; } Hi;
        Hi.h4[0] = __float2half_rn(a0);
        Hi.h4[1] = __float2half_rn(a1);
        Hi.h4[2] = __float2half_rn(a2);
        Hi.h4[3] = __float2half_rn(a3);
        *(uint2*)(g_Wh + er * 256 + c0 + c8 * 4) = Hi.u;
    }
}

// ============================================================================
// K2: out = y @ W^T + bias; single fp16 term, fp32 accum.
//   CTA 128x128, B resident, A 3-slot ring. NOW FULLY UNROLLED kc loop.
// ============================================================================
#define B_STRIDE 528
#define B_BYTES  (128 * B_STRIDE)        // 67584
#define A_SLOT   10240                   // 128 * 80
#define SMEM_TOTAL (B_BYTES + 3 * A_SLOT)  // 98304 (96KB) -> 2 CTAs/SM

__global__ __launch_bounds__(256, 2) void gemm_mma_kernel(const float* __restrict__ bias,
                                                          float* __restrict__ out) {
    extern __shared__ __align__(16) char smem[];
    uint32_t sbB = smem_u32(smem);
    uint32_t sbA = sbB + B_BYTES;
    int tid  = threadIdx.x;
    int wid  = tid >> 5;
    int lane = tid & 31;
    int bn = blockIdx.x * 128;
    int bm = blockIdx.y * 128;
    int wn = wid & 1;
    int wm = wid >> 1;

    float acc[2][8][4] = {};

    #pragma unroll
    for (int i = 0; i < 16; i++) {
        int q = i * 256 + tid;
        int row = q >> 5, c16 = q & 31;
        CP_ASYNC16(sbB + row * B_STRIDE + c16 * 16,
                   gmem_u64(g_Wh + (size_t)(bn + row) * 256 + c16 * 8));
    }

    auto issue_A = [&](int kc, int slot) {
        #pragma unroll
        for (int j = 0; j < 2; j++) {
            int q = tid * 2 + j;
            int row = q >> 2, seg = q & 3;
            CP_ASYNC16(sbA + slot * A_SLOT + row * 80 + seg * 16,
                       gmem_u64(g_yh + (size_t)(bm + row) * 256 + kc * 32 + seg * 8));
        }
    };

    issue_A(0, 0); CP_COMMIT();
    issue_A(1, 1); CP_COMMIT();

    #pragma unroll
    for (int kc = 0; kc < 8; kc++) {
        if (kc < 7) { CP_WAIT(1); } else { CP_WAIT(0); }
        __syncthreads();
        if (kc + 2 < 8) { issue_A(kc + 2, (kc + 2) % 3); CP_COMMIT(); }

        uint32_t aB = sbA + (kc % 3) * A_SLOT;

        #pragma unroll
        for (int ks = 0; ks < 2; ks++) {
            uint32_t af[2][4], bf[4][4];
            #pragma unroll
            for (int mi = 0; mi < 2; mi++) {
                int row = wm * 32 + mi * 16 + (lane & 15);
                uint32_t ao = row * 80 + ks * 32 + (lane >> 4) * 16;
                LDMATRIX_X4(af[mi][0], af[mi][1], af[mi][2], af[mi][3], aB + ao);
            }
            #pragma unroll
            for (int ng = 0; ng < 4; ng++) {
                int row = wn * 64 + ng * 16 + (lane & 15);
                uint32_t bo = row * B_STRIDE + kc * 64 + ks * 32 + (lane >> 4) * 16;
                LDMATRIX_X4(bf[ng][0], bf[ng][1], bf[ng][2], bf[ng][3], sbB + bo);
            }
            #pragma unroll
            for (int mi = 0; mi < 2; mi++)
                #pragma unroll
                for (int ng = 0; ng < 4; ng++) {
                    MMA_16816_F16(acc[mi][ng * 2 + 0], af[mi], bf[ng][0], bf[ng][2]);
                    MMA_16816_F16(acc[mi][ng * 2 + 1], af[mi], bf[ng][1], bf[ng][3]);
                }
        }
    }

    #pragma unroll
    for (int mi = 0; mi < 2; mi++) {
        int r0 = bm + wm * 32 + mi * 16 + (lane >> 2);
        #pragma unroll
        for (int ni = 0; ni < 8; ni++) {
            int c = bn + wn * 64 + ni * 8 + (lane & 3) * 2;
            float b0 = __ldg(bias + c);
            float b1 = __ldg(bias + c + 1);
            float2 o0 = make_float2(acc[mi][ni][0] + b0, acc[mi][ni][1] + b1);
            float2 o1 = make_float2(acc[mi][ni][2] + b0, acc[mi][ni][3] + b1);
            *(float2*)(out + (size_t)r0 * 256 + c) = o0;
            *(float2*)(out + (size_t)(r0 + 8) * 256 + c) = o1;
        }
    }
}

// ============================================================================
extern "C" void kernel_launch(void* const* d_in, const int* in_sizes, int n_in,
                              void* d_out, int out_size) {
    const float* x  = (const float*)d_in[0];
    const float* vw = (const float*)d_in[1];
    const float* pw = (const float*)d_in[2];
    const float* pb = (const float*)d_in[3];
    float* out = (float*)d_out;

    cudaFuncSetAttribute(gemm_mma_kernel, cudaFuncAttributeMaxDynamicSharedMemorySize, SMEM_TOTAL);

    prep_kernel<<<512 + 64, 256>>>(x, vw, pw);
    gemm_mma_kernel<<<dim3(2, 256), 256, SMEM_TOTAL>>>(pb, out);
}

// round 16
// speedup vs baseline: 1.8172x; 1.0432x over previous
#include <cuda_runtime.h>
#include <cuda_fp16.h>
#include <stdint.h>
#include <math.h>

#define BB 8
#define HH 64
#define WW 64
#define CC 256
#define NPIX (BB*HH*WW)          // 32768

// ---------------- device scratch ----------------
__device__ __half g_yh[NPIX*CC];   // blurred x, fp16
__device__ __half g_Wh[CC*CC];     // fused weight W = proj_w @ v_w, fp16

// ---------------- helpers ----------------
__device__ __forceinline__ uint32_t smem_u32(const void* p) {
    uint32_t a;
    asm("{ .reg .u64 t; cvta.to.shared.u64 t, %1; cvt.u32.u64 %0, t; }" : "=r"(a) : "l"(p));
    return a;
}
__device__ __forceinline__ uint64_t gmem_u64(const void* p) {
    uint64_t a;
    asm("cvta.to.global.u64 %0, %1;" : "=l"(a) : "l"(p));
    return a;
}
#define CP_ASYNC16(sa, ga) \
    asm volatile("cp.async.cg.shared.global [%0], [%1], 16;" :: "r"(sa), "l"(ga))
#define CP_COMMIT() asm volatile("cp.async.commit_group;")
#define CP_WAIT(n)  asm volatile("cp.async.wait_group %0;" :: "n"(n))

#define LDMATRIX_X4(r0, r1, r2, r3, addr) \
    asm volatile("ldmatrix.sync.aligned.m8n8.x4.shared.b16 {%0,%1,%2,%3}, [%4];" \
        : "=r"(r0), "=r"(r1), "=r"(r2), "=r"(r3) : "r"(addr))

#define MMA_16816_F16(c, a, b0, b1) \
    asm volatile("mma.sync.aligned.m16n8k16.row.col.f32.f16.f16.f32 " \
        "{%0,%1,%2,%3}, {%4,%5,%6,%7}, {%8,%9}, {%0,%1,%2,%3};" \
        : "+f"((c)[0]), "+f"((c)[1]), "+f"((c)[2]), "+f"((c)[3]) \
        : "r"((a)[0]), "r"((a)[1]), "r"((a)[2]), "r"((a)[3]), "r"(b0), "r"(b1))

static __device__ __forceinline__ float4 f4add(float4 a, float4 b) {
    return make_float4(a.x+b.x, a.y+b.y, a.z+b.z, a.w+b.w);
}

// ============================================================================
// K1: prep (R13 version — validated 19.3us).
//  Blocks [0,512): blur -> g_yh. 6-slot smem ring + dist-5 register queue.
//  Blocks [512,576): W = proj_w @ v_w, smem-staged vw panel.
// ============================================================================
__global__ __launch_bounds__(256) void prep_kernel(const float* __restrict__ x,
                                                   const float* __restrict__ vw,
                                                   const float* __restrict__ pw) {
    __shared__ __align__(16) char sbuf[8 * 257 * 16];   // 32896B
    int bid = blockIdx.x;
    int tid = threadIdx.x;
    if (bid < 512) {
        float4* srow = (float4*)sbuf;     // 6 slots x 256 float4
        int b   = bid >> 6;
        int seg = (bid >> 4) & 3;
        int cg  = bid & 15;
        int h0  = seg * 16;
        int w   = tid >> 2;
        int c4i = tid & 3;
        int c4  = cg * 4 + c4i;
        const float e  = 2.718281828459045f;
        const float wo = 1.0f / (e + 8.0f);
        const float wd = e * wo - wo;
        const float4 Z = make_float4(0.f, 0.f, 0.f, 0.f);
        const float4* x4 = (const float4*)x;

        auto gload = [&](int r) -> float4 {
            if (r < 0 || r >= HH) return Z;
            return x4[(((size_t)b * HH + r) * WW + w) * 64 + c4];
        };

        float4 q[6];
        #pragma unroll
        for (int j = 0; j < 5; j++) q[j] = gload(h0 - 1 + j);

        float4 hs0 = Z, hs1 = Z, xl0 = Z, xl1 = Z;

        #pragma unroll
        for (int i = 0; i < 18; i++) {          // row r = h0-1+i
            int slot = i % 6;
            srow[slot * 256 + w * 4 + c4i] = q[i % 6];
            if (i + 5 < 18) q[(i + 5) % 6] = gload(h0 - 1 + i + 5);
            __syncthreads();

            float4 xl = (w > 0)  ? srow[slot * 256 + (w - 1) * 4 + c4i] : Z;
            float4 xc =            srow[slot * 256 + w * 4 + c4i];
            float4 xr = (w < 63) ? srow[slot * 256 + (w + 1) * 4 + c4i] : Z;
            float4 hsum = f4add(f4add(xl, xc), xr);

            if (i >= 2) {
                int h = h0 + i - 2;
                float4 o;
                o.x = wo * (hs0.x + hs1.x + hsum.x) + wd * xl0.x;
                o.y = wo * (hs0.y + hs1.y + hsum.y) + wd * xl0.y;
                o.z = wo * (hs0.z + hs1.z + hsum.z) + wd * xl0.z;
                o.w = wo * (hs0.w + hs1.w + hsum.w) + wd * xl0.w;
                union { __half h4[4]; uint2 u; } Hi;
                Hi.h4[0] = __float2half_rn(o.x);
                Hi.h4[1] = __float2half_rn(o.y);
                Hi.h4[2] = __float2half_rn(o.z);
                Hi.h4[3] = __float2half_rn(o.w);
                size_t oq = (((size_t)b * HH + h) * WW + w) * 64 + c4;
                ((uint2*)g_yh)[oq] = Hi.u;
            }
            hs0 = hs1; hs1 = hsum;
            xl0 = xl1; xl1 = xl;
        }
    } else {
        // ---- W-fuse: smem-staged vw panel ----
        float4* Bs4 = (float4*)sbuf;          // [chunk 0..7][d 0..255], stride 257
        int q  = bid - 512;
        int e0 = (q >> 3) * 32;
        int c0 = (q & 7) * 32;
        const float4* vw4 = (const float4*)vw;
        #pragma unroll
        for (int j = 0; j < 8; j++)
            Bs4[j * 257 + tid] = vw4[tid * 64 + (c0 >> 2) + j];
        __syncthreads();

        int er = e0 + (tid >> 3);
        int c8 = tid & 7;
        const float* prow = pw + er * 256;
        const float4* Bcol = Bs4 + c8 * 257;
        float a0 = 0.f, a1 = 0.f, a2 = 0.f, a3 = 0.f;
        #pragma unroll 8
        for (int d = 0; d < 256; d++) {
            float a = prow[d];
            float4 bv = Bcol[d];
            a0 += a * bv.x; a1 += a * bv.y; a2 += a * bv.z; a3 += a * bv.w;
        }
        union { __half h4[4]; uint2 u; } Hi;
        Hi.h4[0] = __float2half_rn(a0);
        Hi.h4[1] = __float2half_rn(a1);
        Hi.h4[2] = __float2half_rn(a2);
        Hi.h4[3] = __float2half_rn(a3);
        *(uint2*)(g_Wh + er * 256 + c0 + c8 * 4) = Hi.u;
    }
}

// ============================================================================
// K2: out = y @ W^T + bias; single fp16 term, fp32 accum.
//   PERSISTENT 2-TILE CTA: grid (2,128) = 256 CTAs (single wave at 2/SM).
//   Each CTA: B N-panel resident (loaded once), processes M-tiles
//   bm = by*128 and bm+16384 through ONE uniform 16-round cp.async pipeline
//   (tile-1 chunks prefetched during tile-0's last rounds; epilogue-0
//   overlaps their latency). A: 3-slot ring, slot = global_chunk % 3.
// ============================================================================
#define B_STRIDE 528
#define B_BYTES  (128 * B_STRIDE)        // 67584
#define A_SLOT   10240                   // 128 * 80
#define SMEM_TOTAL (B_BYTES + 3 * A_SLOT)  // 98304 (96KB) -> 2 CTAs/SM

__global__ __launch_bounds__(256, 2) void gemm_mma_kernel(const float* __restrict__ bias,
                                                          float* __restrict__ out) {
    extern __shared__ __align__(16) char smem[];
    uint32_t sbB = smem_u32(smem);
    uint32_t sbA = sbB + B_BYTES;
    int tid  = threadIdx.x;
    int wid  = tid >> 5;
    int lane = tid & 31;
    int bn = blockIdx.x * 128;
    int by = blockIdx.y;               // 0..127
    int wn = wid & 1;
    int wm = wid >> 1;

    float acc[2][8][4] = {};

    // ---- one-time B load: 128 rows x 512B ----
    #pragma unroll
    for (int i = 0; i < 16; i++) {
        int q = i * 256 + tid;
        int row = q >> 5, c16 = q & 31;
        CP_ASYNC16(sbB + row * B_STRIDE + c16 * 16,
                   gmem_u64(g_Wh + (size_t)(bn + row) * 256 + c16 * 8));
    }

    // chunk n in [0,16): tile = n>>3, kc = n&7, slot = n%3
    auto issue_A = [&](int n) {
        int kc = n & 7;
        int slot = n % 3;
        size_t bm = (size_t)by * 128 + (size_t)(n >> 3) * 16384;
        #pragma unroll
        for (int j = 0; j < 2; j++) {
            int q = tid * 2 + j;
            int row = q >> 2, seg = q & 3;
            CP_ASYNC16(sbA + slot * A_SLOT + row * 80 + seg * 16,
                       gmem_u64(g_yh + (bm + row) * 256 + kc * 32 + seg * 8));
        }
    };

    issue_A(0); CP_COMMIT();     // group 0 = B + chunk0
    issue_A(1); CP_COMMIT();     // group 1 = chunk1

    #pragma unroll
    for (int t = 0; t < 2; t++) {
        #pragma unroll
        for (int kc = 0; kc < 8; kc++) {
            int r = t * 8 + kc;
            if (r < 15) { CP_WAIT(1); } else { CP_WAIT(0); }
            __syncthreads();
            if (r + 2 < 16) issue_A(r + 2);
            CP_COMMIT();                    // commit every round (uniform counting)

            uint32_t aB = sbA + (r % 3) * A_SLOT;

            #pragma unroll
            for (int ks = 0; ks < 2; ks++) {
                uint32_t af[2][4], bf[4][4];
                #pragma unroll
                for (int mi = 0; mi < 2; mi++) {
                    int row = wm * 32 + mi * 16 + (lane & 15);
                    uint32_t ao = row * 80 + ks * 32 + (lane >> 4) * 16;
                    LDMATRIX_X4(af[mi][0], af[mi][1], af[mi][2], af[mi][3], aB + ao);
                }
                #pragma unroll
                for (int ng = 0; ng < 4; ng++) {
                    int row = wn * 64 + ng * 16 + (lane & 15);
                    uint32_t bo = row * B_STRIDE + kc * 64 + ks * 32 + (lane >> 4) * 16;
                    LDMATRIX_X4(bf[ng][0], bf[ng][1], bf[ng][2], bf[ng][3], sbB + bo);
                }
                #pragma unroll
                for (int mi = 0; mi < 2; mi++)
                    #pragma unroll
                    for (int ng = 0; ng < 4; ng++) {
                        MMA_16816_F16(acc[mi][ng * 2 + 0], af[mi], bf[ng][0], bf[ng][2]);
                        MMA_16816_F16(acc[mi][ng * 2 + 1], af[mi], bf[ng][1], bf[ng][3]);
                    }
            }
        }

        // ---- epilogue for tile t (overlaps tile-1 chunk loads when t==0) ----
        size_t bmt = (size_t)by * 128 + (size_t)t * 16384;
        #pragma unroll
        for (int mi = 0; mi < 2; mi++) {
            size_t r0 = bmt + wm * 32 + mi * 16 + (lane >> 2);
            #pragma unroll
            for (int ni = 0; ni < 8; ni++) {
                int c = bn + wn * 64 + ni * 8 + (lane & 3) * 2;
                float b0 = __ldg(bias + c);
                float b1 = __ldg(bias + c + 1);
                float2 o0 = make_float2(acc[mi][ni][0] + b0, acc[mi][ni][1] + b1);
                float2 o1 = make_float2(acc[mi][ni][2] + b0, acc[mi][ni][3] + b1);
                *(float2*)(out + r0 * 256 + c) = o0;
                *(float2*)(out + (r0 + 8) * 256 + c) = o1;
            }
        }
        if (t == 0) {
            #pragma unroll
            for (int mi = 0; mi < 2; mi++)
                #pragma unroll
                for (int ni = 0; ni < 8; ni++)
                    #pragma unroll
                    for (int v = 0; v < 4; v++) acc[mi][ni][v] = 0.f;
        }
    }
}

// ============================================================================
extern "C" void kernel_launch(void* const* d_in, const int* in_sizes, int n_in,
                              void* d_out, int out_size) {
    const float* x  = (const float*)d_in[0];
    const float* vw = (const float*)d_in[1];
    const float* pw = (const float*)d_in[2];
    const float* pb = (const float*)d_in[3];
    float* out = (float*)d_out;

    cudaFuncSetAttribute(gemm_mma_kernel, cudaFuncAttributeMaxDynamicSharedMemorySize, SMEM_TOTAL);

    prep_kernel<<<512 + 64, 256>>>(x, vw, pw);
    gemm_mma_kernel<<<dim3(2, 128), 256, SMEM_TOTAL>>>(pb, out);
}